// round 8
// baseline (speedup 1.0000x reference)
#include <cuda_runtime.h>
#include <cuda_fp16.h>
#include <math.h>
#include <stdint.h>

#define PP 256
#define TT 65536
#define UU 128
#define NC 512            // 128-t spans in phase1
#define NCS 2048          // scan chunks (32 t each)
#define NU 1024           // gemm work units per p-tile (64 t each)

// ---------------- device scratch ----------------
__device__ __align__(16) float g_L[PP*NCS];
__device__ __align__(16) float g_H[PP*NCS];
__device__ __align__(16) float g_sin[PP*NCS];
__device__ __align__(16) float g_y[PP*UU];
__device__ __align__(16) __half g_kh[(size_t)UU*TT];   // [U][T] fp16
__device__ int g_tick[2];

// ---------------- helpers ----------------
__device__ __forceinline__ uint32_t smem_u32(const void* p) {
    uint32_t a;
    asm("{ .reg .u64 t; cvta.to.shared.u64 t, %1; cvt.u32.u64 %0, t; }" : "=r"(a) : "l"(p));
    return a;
}
__device__ __forceinline__ void cp16(uint32_t dst, const void* src) {
    asm volatile("cp.async.cg.shared.global [%0], [%1], 16;" :: "r"(dst), "l"(src));
}
#define CP_COMMIT() asm volatile("cp.async.commit_group;" ::: "memory")
#define CP_WAIT0()  asm volatile("cp.async.wait_group 0;" ::: "memory")

#define LDSM_X4(d, addr) \
    asm volatile("ldmatrix.sync.aligned.m8n8.x4.shared.b16 {%0,%1,%2,%3}, [%4];" \
        : "=r"((d)[0]), "=r"((d)[1]), "=r"((d)[2]), "=r"((d)[3]) : "r"(addr))

#define MMA_F16(c, a, b0, b1) \
    asm volatile("mma.sync.aligned.m16n8k16.row.col.f32.f16.f16.f32 " \
        "{%0,%1,%2,%3}, {%4,%5,%6,%7}, {%8,%9}, {%0,%1,%2,%3};" \
        : "+f"((c)[0]), "+f"((c)[1]), "+f"((c)[2]), "+f"((c)[3]) \
        : "r"((a)[0]), "r"((a)[1]), "r"((a)[2]), "r"((a)[3]), "r"(b0), "r"(b1))

__device__ __forceinline__ void combine(float& l, float& h, float l2, float h2) {
    l = fminf(fmaxf(l, l2), h2);
    h = fminf(fmaxf(h, l2), h2);
}

// ============================================================
// Phase 1 (fused): 32-t chunk reductions + kernel transpose (fp16)
// ============================================================
__global__ void k_phase1(const float* __restrict__ x, const float* __restrict__ w,
                         const float* __restrict__ kern) {
    if (blockIdx.x < (PP * NC) / 8) {
        // one warp per 128-t span; produces FOUR 32-t (L,H) pairs
        int wid  = (blockIdx.x * blockDim.x + threadIdx.x) >> 5;
        int lane = threadIdx.x & 31;
        int p = wid >> 9;
        int c = wid & (NC - 1);

        float wp = __ldg(&w[p]);
        const float4 xv = *(const float4*)(x + (size_t)p * TT + (size_t)c * 128 + lane * 4);
        float x0 = xv.x * wp, x1 = xv.y * wp, x2 = xv.z * wp, x3 = xv.w * wp;

        float l = x0, h = x0 + 1.0f;
        combine(l, h, x1, x1 + 1.0f);
        combine(l, h, x2, x2 + 1.0f);
        combine(l, h, x3, x3 + 1.0f);
        // reduce within 8-lane groups (32 t each)
        #pragma unroll
        for (int d = 1; d < 8; d <<= 1) {
            float lo = __shfl_down_sync(0xffffffffu, l, d);
            float ho = __shfl_down_sync(0xffffffffu, h, d);
            if ((lane & 7) + d < 8) combine(l, h, lo, ho);
        }
        if ((lane & 7) == 0) {
            int c4 = c * 4 + (lane >> 3);
            g_L[p * NCS + c4] = l;
            g_H[p * NCS + c4] = h;
        }
    } else {
        __shared__ __half sh[128][72];
        int tb = blockIdx.x - (PP * NC) / 8;
        int t0 = tb * 64;
        int u = threadIdx.x & 127, rh = threadIdx.x >> 7;
        #pragma unroll 8
        for (int rr = 0; rr < 64; rr += 2) {
            int t = t0 + rr + rh;
            sh[u][rr + rh] = __float2half_rn(__ldg(&kern[(size_t)t * UU + u]));
        }
        __syncthreads();
        int uu = threadIdx.x >> 1, half_ = threadIdx.x & 1;
        const uint4* srcH = (const uint4*)&sh[uu][half_ * 32];
        uint4* dstH = (uint4*)(g_kh + (size_t)uu * TT + t0 + half_ * 32);
        #pragma unroll
        for (int q = 0; q < 4; q++) dstH[q] = srcH[q];
    }
}

// ============================================================
// Phase 2: per-player scan over 2048 chunk-ops (+ zero g_y, g_tick)
// Warp per player; lane owns 64 consecutive chunks (streamed twice).
// ============================================================
__global__ void k_scan(const float* __restrict__ state) {
    int gtid = blockIdx.x * blockDim.x + threadIdx.x;   // 0..8191
    ((float4*)g_y)[gtid] = make_float4(0.f, 0.f, 0.f, 0.f);
    if (gtid < 2) g_tick[gtid] = 0;

    int p    = gtid >> 5;
    int lane = gtid & 31;
    int base = p * NCS + lane * 64;

    // pass A: compose this lane's 64 chunk-ops
    float l = g_L[base], h = g_H[base];
    #pragma unroll 4
    for (int i = 1; i < 64; i++) combine(l, h, g_L[base + i], g_H[base + i]);

    // warp inclusive scan
    #pragma unroll
    for (int d = 1; d < 32; d <<= 1) {
        float lo = __shfl_up_sync(0xffffffffu, l, d);
        float ho = __shfl_up_sync(0xffffffffu, h, d);
        if (lane >= d) {
            float nl = fminf(fmaxf(lo, l), h);
            float nh = fminf(fmaxf(ho, l), h);
            l = nl; h = nh;
        }
    }
    float exl = __shfl_up_sync(0xffffffffu, l, 1);
    float exh = __shfl_up_sync(0xffffffffu, h, 1);

    float s = state[p];
    if (lane > 0) s = fminf(fmaxf(s, exl), exh);

    // pass B: replay, emitting incoming state per 32-t chunk
    #pragma unroll 4
    for (int i = 0; i < 64; i++) {
        g_sin[base + i] = s;
        s = fminf(fmaxf(s, g_L[base + i]), g_H[base + i]);
    }
}

// ============================================================
// Phase 3: work-stealing fp16 HMMA GEMM with fused replay.
// Unit = (p-tile fixed per block, 64-t chunk via ticket).
// A: 16KB [128p][64t]; B: 2-slot 16KB ring. 48KB smem, 2 blocks/SM.
// Scan: 256 threads = (player, t-half), 32 serial steps each.
// ============================================================
#define B_OFF  16384
#define B_SLOT 16384
#define SMEM_TOT (B_OFF + 2 * B_SLOT)    // 49152

__global__ void __launch_bounds__(256, 2)
k_gemm(const float* __restrict__ x, const float* __restrict__ w) {
    __shared__ int s_tk;
    extern __shared__ char smem[];
    const uint32_t sb = smem_u32(smem);
    const int tid  = threadIdx.x;
    const int warp = tid >> 5;
    const int lane = tid & 31;
    const int py = blockIdx.y;
    const int p0 = py * 128;
    const int rg = warp >> 1;            // MMA: player group (32)
    const int cg = warp & 1;             // MMA: unit group (64)

    float acc[2][8][4];
    #pragma unroll
    for (int a = 0; a < 2; a++)
        #pragma unroll
        for (int b = 0; b < 8; b++)
            #pragma unroll
            for (int r = 0; r < 4; r++) acc[a][b][r] = 0.f;

    // scan-side constants: thread = (player, t-half)
    const int pl = tid & 127;
    const int hf = tid >> 7;
    const int p  = p0 + pl;
    const float wp = __ldg(&w[p]);
    const uint32_t aRowS = (uint32_t)pl * 128;
    const uint32_t sxor  = (uint32_t)(pl & 7);

    // MMA-side constants
    const uint32_t aRowM = (uint32_t)(rg * 32 + (lane & 15)) * 128;
    const int laneKA = lane >> 4;
    const uint32_t bRowM = (uint32_t)(cg * 64 + (lane & 7) + 8 * (lane >> 4)) * 128;
    const int laneKB = (lane >> 3) & 1;
    const uint32_t lxor = (uint32_t)(lane & 7);

    // B loader: 128u x 64t fp16 -> slot (1024 x 16B)
    auto loadB = [&](int c64, int slot) {
        uint32_t dbase = sb + B_OFF + slot * B_SLOT;
        #pragma unroll
        for (int q = 0; q < 4; q++) {
            int idx = q * 256 + tid;          // 0..1023
            int u = idx >> 3, seg = idx & 7;
            cp16(dbase + u * 128 + (((uint32_t)(seg ^ (u & 7))) << 4),
                 (const char*)(g_kh + (size_t)u * TT + (size_t)c64 * 64 + seg * 8));
        }
    };

    // ---- prologue: grab first ticket, prefetch its B ----
    if (tid == 0) s_tk = atomicAdd(&g_tick[py], 1);
    __syncthreads();
    int cur = s_tk;
    int slot = 0;
    if (cur < NU) loadB(cur, 0);
    CP_COMMIT();

    while (cur < NU) {
        if (tid == 0) s_tk = atomicAdd(&g_tick[py], 1);

        // ---- lane-serial replay: 32 clamp steps into A ----
        {
            float s = __ldg(&g_sin[(size_t)p * NCS + cur * 2 + hf]);
            const float4* xr = (const float4*)(x + (size_t)p * TT + cur * 64 + hf * 32);
            #pragma unroll
            for (int g = 0; g < 4; g++) {
                float4 v0 = __ldg(xr + 2 * g);
                float4 v1 = __ldg(xr + 2 * g + 1);
                float xs[8] = { v0.x*wp, v0.y*wp, v0.z*wp, v0.w*wp,
                                v1.x*wp, v1.y*wp, v1.z*wp, v1.w*wp };
                float ss[8];
                #pragma unroll
                for (int t2 = 0; t2 < 8; t2++) {
                    s = fminf(fmaxf(s, xs[t2]), xs[t2] + 1.0f);
                    ss[t2] = s;
                }
                uint32_t hw[4];
                #pragma unroll
                for (int j = 0; j < 4; j++) {
                    asm("cvt.rn.f16x2.f32 %0, %1, %2;"
                        : "=r"(hw[j]) : "f"(ss[2*j+1]), "f"(ss[2*j]));
                }
                uint32_t seg = (uint32_t)(hf * 4 + g);
                uint32_t ad = sb + aRowS + ((seg ^ sxor) << 4);
                asm volatile("st.shared.v4.b32 [%0], {%1,%2,%3,%4};"
                    :: "r"(ad), "r"(hw[0]), "r"(hw[1]), "r"(hw[2]), "r"(hw[3]) : "memory");
            }
        }

        CP_WAIT0();            // B(cur) resident
        __syncthreads();       // A stores + B + s_tk visible

        int nxt = s_tk;
        if (nxt < NU) loadB(nxt, slot ^ 1);   // prefetch next unit's B
        CP_COMMIT();

        // ---- MMA: 4 k-steps of 16 over [128p] x [128u] x 64t ----
        const uint32_t BS = sb + B_OFF + (uint32_t)slot * B_SLOT;
        #pragma unroll
        for (int ks = 0; ks < 4; ks++) {
            uint32_t ao = (((uint32_t)(ks * 2 + laneKA)) ^ lxor) << 4;
            uint32_t a0[4], a1[4];
            LDSM_X4(a0, sb + aRowM + ao);
            LDSM_X4(a1, sb + aRowM + 2048 + ao);

            uint32_t bo = (((uint32_t)(ks * 2 + laneKB)) ^ lxor) << 4;
            #pragma unroll
            for (int q = 0; q < 4; q++) {
                uint32_t bh[4];
                LDSM_X4(bh, BS + bRowM + q * 2048 + bo);
                #pragma unroll
                for (int t2 = 0; t2 < 2; t2++) {
                    int nt = 2 * q + t2;
                    MMA_F16(acc[0][nt], a0, bh[2*t2], bh[2*t2+1]);
                    MMA_F16(acc[1][nt], a1, bh[2*t2], bh[2*t2+1]);
                }
            }
        }

        __syncthreads();       // MMA done reading A/B before overwrite
        cur = nxt;
        slot ^= 1;
    }

    // ---- single atomic pass ----
    #pragma unroll
    for (int mt = 0; mt < 2; mt++) {
        #pragma unroll
        for (int nt = 0; nt < 8; nt++) {
            #pragma unroll
            for (int r = 0; r < 4; r++) {
                int row = p0 + rg * 32 + mt * 16 + (lane >> 2) + ((r >> 1) ? 8 : 0);
                int col = cg * 64 + nt * 8 + (lane & 3) * 2 + (r & 1);
                atomicAdd(&g_y[row * UU + col], acc[mt][nt][r]);
            }
        }
    }
}

// ============================================================
// Phase 4: epilogue  out = tanh(y + bias)
// ============================================================
__global__ void k_out(const float* __restrict__ bias, float* __restrict__ out) {
    int i = blockIdx.x * blockDim.x + threadIdx.x;
    float4 v = ((const float4*)g_y)[i];
    float4 b = ((const float4*)bias)[i & 31];
    float4 o;
    o.x = tanhf(v.x + b.x); o.y = tanhf(v.y + b.y);
    o.z = tanhf(v.z + b.z); o.w = tanhf(v.w + b.w);
    ((float4*)out)[i] = o;
}

// ============================================================
extern "C" void kernel_launch(void* const* d_in, const int* in_sizes, int n_in,
                              void* d_out, int out_size) {
    const float* inputs = (const float*)d_in[0];
    const float* pw     = (const float*)d_in[1];
    const float* kern   = (const float*)d_in[2];
    const float* bias   = (const float*)d_in[3];
    const float* state  = (const float*)d_in[4];
    float* out = (float*)d_out;

    cudaFuncSetAttribute(k_gemm, cudaFuncAttributeMaxDynamicSharedMemorySize, SMEM_TOT);

    k_phase1<<<(PP * NC) / 8 + TT / 64, 256>>>(inputs, pw, kern);
    k_scan<<<32, 256>>>(state);
    k_gemm<<<dim3(148, 2), 256, SMEM_TOT>>>(inputs, pw);
    k_out<<<32, 256>>>(bias, out);
}

// round 9
// speedup vs baseline: 1.1697x; 1.1697x over previous
#include <cuda_runtime.h>
#include <cuda_fp16.h>
#include <math.h>
#include <stdint.h>

#define PP 256
#define TT 65536
#define UU 128
#define TC 128            // GEMM chunk (t)
#define NC 512            // GEMM chunks
#define NCS 1024          // scan chunks (64 t each)

// ---------------- device scratch ----------------
__device__ __align__(16) float g_L[PP*NCS];
__device__ __align__(16) float g_H[PP*NCS];
__device__ __align__(16) float g_sin[PP*NCS];
__device__ __align__(16) float g_y[PP*UU];
__device__ __align__(16) __half g_kh[(size_t)UU*TT];   // [U][T] fp16 kernel^T
__device__ __align__(16) __half g_xh[(size_t)PP*TT];   // [P][T] fp16 x*w

// ---------------- helpers ----------------
__device__ __forceinline__ uint32_t smem_u32(const void* p) {
    uint32_t a;
    asm("{ .reg .u64 t; cvta.to.shared.u64 t, %1; cvt.u32.u64 %0, t; }" : "=r"(a) : "l"(p));
    return a;
}
__device__ __forceinline__ void cp16(uint32_t dst, const void* src) {
    asm volatile("cp.async.cg.shared.global [%0], [%1], 16;" :: "r"(dst), "l"(src));
}
#define CP_COMMIT() asm volatile("cp.async.commit_group;" ::: "memory")
#define CP_WAIT1()  asm volatile("cp.async.wait_group 1;" ::: "memory")
#define CP_WAIT0()  asm volatile("cp.async.wait_group 0;" ::: "memory")

#define LDSM_X4(d, addr) \
    asm volatile("ldmatrix.sync.aligned.m8n8.x4.shared.b16 {%0,%1,%2,%3}, [%4];" \
        : "=r"((d)[0]), "=r"((d)[1]), "=r"((d)[2]), "=r"((d)[3]) : "r"(addr))

#define MMA_F16(c, a, b0, b1) \
    asm volatile("mma.sync.aligned.m16n8k16.row.col.f32.f16.f16.f32 " \
        "{%0,%1,%2,%3}, {%4,%5,%6,%7}, {%8,%9}, {%0,%1,%2,%3};" \
        : "+f"((c)[0]), "+f"((c)[1]), "+f"((c)[2]), "+f"((c)[3]) \
        : "r"((a)[0]), "r"((a)[1]), "r"((a)[2]), "r"((a)[3]), "r"(b0), "r"(b1))

__device__ __forceinline__ void combine(float& l, float& h, float l2, float h2) {
    l = fminf(fmaxf(l, l2), h2);
    h = fminf(fmaxf(h, l2), h2);
}

// ============================================================
// Phase 1 (fused): 64-t chunk reductions + fp16 x*w store
//                  + kernel transpose (fp16)
// ============================================================
__global__ void k_phase1(const float* __restrict__ x, const float* __restrict__ w,
                         const float* __restrict__ kern) {
    if (blockIdx.x < (PP * NC) / 8) {
        int wid  = (blockIdx.x * blockDim.x + threadIdx.x) >> 5;
        int lane = threadIdx.x & 31;
        int p = wid >> 9;
        int c = wid & (NC - 1);

        float wp = __ldg(&w[p]);
        const float4 xv = *(const float4*)(x + (size_t)p * TT + (size_t)c * TC + lane * 4);
        float x0 = xv.x * wp, x1 = xv.y * wp, x2 = xv.z * wp, x3 = xv.w * wp;

        // store fp16 scaled x for the gemm replay
        uint32_t wa, wb;
        asm("cvt.rn.f16x2.f32 %0, %1, %2;" : "=r"(wa) : "f"(x1), "f"(x0));
        asm("cvt.rn.f16x2.f32 %0, %1, %2;" : "=r"(wb) : "f"(x3), "f"(x2));
        *(uint2*)(g_xh + (size_t)p * TT + (size_t)c * TC + lane * 4) = make_uint2(wa, wb);

        float l = x0, h = x0 + 1.0f;
        combine(l, h, x1, x1 + 1.0f);
        combine(l, h, x2, x2 + 1.0f);
        combine(l, h, x3, x3 + 1.0f);
        #pragma unroll
        for (int d = 1; d < 16; d <<= 1) {
            float lo = __shfl_down_sync(0xffffffffu, l, d);
            float ho = __shfl_down_sync(0xffffffffu, h, d);
            if ((lane & 15) + d < 16) combine(l, h, lo, ho);
        }
        if ((lane & 15) == 0) {
            int c2 = c * 2 + (lane >> 4);
            g_L[p * NCS + c2] = l;
            g_H[p * NCS + c2] = h;
        }
    } else {
        __shared__ __half sh[128][72];
        int tb = blockIdx.x - (PP * NC) / 8;
        int t0 = tb * 64;
        int u = threadIdx.x & 127, rh = threadIdx.x >> 7;
        #pragma unroll 8
        for (int rr = 0; rr < 64; rr += 2) {
            int t = t0 + rr + rh;
            sh[u][rr + rh] = __float2half_rn(__ldg(&kern[(size_t)t * UU + u]));
        }
        __syncthreads();
        int uu = threadIdx.x >> 1, half_ = threadIdx.x & 1;
        const uint4* srcH = (const uint4*)&sh[uu][half_ * 32];
        uint4* dstH = (uint4*)(g_kh + (size_t)uu * TT + t0 + half_ * 32);
        #pragma unroll
        for (int q = 0; q < 4; q++) dstH[q] = srcH[q];
    }
}

// ============================================================
// Phase 2: per-player scan over 1024 chunk-ops (+ zero g_y)
// ============================================================
__global__ void k_scan(const float* __restrict__ state) {
    int gtid = blockIdx.x * blockDim.x + threadIdx.x;
    ((float4*)g_y)[gtid] = make_float4(0.f, 0.f, 0.f, 0.f);

    int p    = gtid >> 5;
    int lane = gtid & 31;
    const int CPL = NCS / 32;

    float L[CPL], H[CPL];
    int base = p * NCS + lane * CPL;
    #pragma unroll
    for (int i = 0; i < CPL; i++) { L[i] = g_L[base + i]; H[i] = g_H[base + i]; }

    float l = L[0], h = H[0];
    #pragma unroll
    for (int i = 1; i < CPL; i++) combine(l, h, L[i], H[i]);

    #pragma unroll
    for (int d = 1; d < 32; d <<= 1) {
        float lo = __shfl_up_sync(0xffffffffu, l, d);
        float ho = __shfl_up_sync(0xffffffffu, h, d);
        if (lane >= d) {
            float nl = fminf(fmaxf(lo, l), h);
            float nh = fminf(fmaxf(ho, l), h);
            l = nl; h = nh;
        }
    }
    float exl = __shfl_up_sync(0xffffffffu, l, 1);
    float exh = __shfl_up_sync(0xffffffffu, h, 1);

    float s = state[p];
    if (lane > 0) s = fminf(fmaxf(s, exl), exh);
    #pragma unroll
    for (int i = 0; i < CPL; i++) {
        g_sin[base + i] = s;
        s = fminf(fmaxf(s, L[i]), H[i]);
    }
}

// ============================================================
// Phase 3: fp16 HMMA GEMM (1 term) with fused lane-serial replay.
// Grid (148,2) -> 2 blocks/SM (96KB smem). ~3.5 chunks/block.
// Replay reads pre-scaled fp16 x (half the bytes, no multiplies).
// ============================================================
#define B_BASE 32768
#define B_SLOT 32768
#define SMEM_TOT (B_BASE + 2 * B_SLOT)   // 96KB

__global__ void __launch_bounds__(256, 2)
k_gemm(const float* __restrict__ xunused) {
    extern __shared__ char smem[];
    const uint32_t sb = smem_u32(smem);
    const int tid  = threadIdx.x;
    const int warp = tid >> 5;
    const int lane = tid & 31;
    const int bx = blockIdx.x;           // 0..147
    const int p0 = blockIdx.y * 128;
    const int rg = warp >> 1;            // MMA: player group (32)
    const int cg = warp & 1;             // MMA: unit group (64)
    const int sub = warp >> 2;           // scan: t-half (0/1)
    const int pg  = warp & 3;            // scan: player group (32)

    float acc[2][8][4];
    #pragma unroll
    for (int a = 0; a < 2; a++)
        #pragma unroll
        for (int b = 0; b < 8; b++)
            #pragma unroll
            for (int r = 0; r < 4; r++) acc[a][b][r] = 0.f;

    const int nch = (511 - bx) / 148 + 1;

    // scan-side constants
    const int pl = pg * 32 + lane;
    const int p  = p0 + pl;
    const uint32_t aRowS = (uint32_t)pl * 256;
    const uint32_t sxor  = (uint32_t)(pl & 15);

    // MMA-side constants
    const uint32_t aRowM = (uint32_t)(rg * 32 + (lane & 15)) * 256;
    const uint32_t axor  = (uint32_t)(lane & 15);
    const int laneKA = lane >> 4;
    const uint32_t bRow = (uint32_t)(cg * 64 + (lane & 7) + 8 * (lane >> 4)) * 256;
    const uint32_t bxor = (uint32_t)(((lane & 7) + 8 * (lane >> 4)) & 15);
    const int laneKB = (lane >> 3) & 1;

    // B loader: 128u x 128t fp16 -> slot
    auto loadB = [&](int c, int slot) {
        uint32_t dbase = sb + B_BASE + slot * B_SLOT;
        #pragma unroll
        for (int q = 0; q < 8; q++) {
            int idx = q * 256 + tid;
            int u = idx >> 4, seg = idx & 15;
            cp16(dbase + u * 256 + (((uint32_t)(seg ^ (u & 15))) << 4),
                 (const char*)(g_kh + (size_t)u * TT + (size_t)c * TC + seg * 8));
        }
    };

    loadB(bx, 0);
    CP_COMMIT();

    for (int i = 0; i < nch; i++) {
        const int c = bx + i * 148;

        __syncthreads();       // previous MMA finished reading A / B slot free

        // ---- lane-serial replay from fp16 x: 64 steps into A ----
        {
            float s = __ldg(&g_sin[(size_t)p * NCS + c * 2 + sub]);
            const uint4* xr = (const uint4*)(g_xh + (size_t)p * TT + (size_t)c * TC + sub * 64);
            if (i + 1 < nch) {
                const __half* nx = g_xh + (size_t)p * TT + (size_t)(c + 148) * TC + sub * 64;
                asm volatile("prefetch.L2 [%0];" :: "l"(nx));
            }
            #pragma unroll
            for (int g = 0; g < 8; g++) {
                uint4 v = __ldg(xr + g);     // 8 halves = 8 t
                float2 f0 = __half22float2(*(const __half2*)&v.x);
                float2 f1 = __half22float2(*(const __half2*)&v.y);
                float2 f2 = __half22float2(*(const __half2*)&v.z);
                float2 f3 = __half22float2(*(const __half2*)&v.w);
                float xs[8] = { f0.x, f0.y, f1.x, f1.y, f2.x, f2.y, f3.x, f3.y };
                float ss[8];
                #pragma unroll
                for (int t2 = 0; t2 < 8; t2++) {
                    s = fminf(fmaxf(s, xs[t2]), xs[t2] + 1.0f);
                    ss[t2] = s;
                }
                uint32_t hw[4];
                #pragma unroll
                for (int j = 0; j < 4; j++) {
                    asm("cvt.rn.f16x2.f32 %0, %1, %2;"
                        : "=r"(hw[j]) : "f"(ss[2*j+1]), "f"(ss[2*j]));
                }
                uint32_t seg = (uint32_t)(sub * 8 + g);
                uint32_t ad = sb + aRowS + ((seg ^ sxor) << 4);
                asm volatile("st.shared.v4.b32 [%0], {%1,%2,%3,%4};"
                    :: "r"(ad), "r"(hw[0]), "r"(hw[1]), "r"(hw[2]), "r"(hw[3]) : "memory");
            }
        }

        if (i + 1 < nch) { loadB(c + 148, (i + 1) & 1); CP_COMMIT(); CP_WAIT1(); }
        else            { CP_WAIT0(); }

        __syncthreads();       // A stores + B(i) visible

        // ---- MMA: 8 k-steps of 16 ----
        const uint32_t BS = sb + B_BASE + (uint32_t)(i & 1) * B_SLOT;
        #pragma unroll
        for (int ks = 0; ks < 8; ks++) {
            uint32_t ao = (((uint32_t)(ks * 2 + laneKA)) ^ axor) << 4;
            uint32_t a0[4], a1[4];
            LDSM_X4(a0, sb + aRowM + ao);
            LDSM_X4(a1, sb + aRowM + 4096 + ao);

            uint32_t bo = (((uint32_t)(ks * 2 + laneKB)) ^ bxor) << 4;
            #pragma unroll
            for (int q = 0; q < 4; q++) {
                uint32_t bh[4];
                LDSM_X4(bh, BS + bRow + q * 4096 + bo);
                #pragma unroll
                for (int t2 = 0; t2 < 2; t2++) {
                    int nt = 2 * q + t2;
                    MMA_F16(acc[0][nt], a0, bh[2*t2], bh[2*t2+1]);
                    MMA_F16(acc[1][nt], a1, bh[2*t2], bh[2*t2+1]);
                }
            }
        }
    }

    // ---- single atomic pass (rotated by bx to spread conflicts) ----
    #pragma unroll
    for (int mt = 0; mt < 2; mt++) {
        #pragma unroll
        for (int ntl = 0; ntl < 8; ntl++) {
            int nt = (ntl + bx) & 7;
            #pragma unroll
            for (int r = 0; r < 4; r++) {
                int row = p0 + rg * 32 + mt * 16 + (lane >> 2) + ((r >> 1) ? 8 : 0);
                int col = cg * 64 + nt * 8 + (lane & 3) * 2 + (r & 1);
                atomicAdd(&g_y[row * UU + col], acc[mt][nt][r]);
            }
        }
    }
}

// ============================================================
// Phase 4: epilogue  out = tanh(y + bias)
// ============================================================
__global__ void k_out(const float* __restrict__ bias, float* __restrict__ out) {
    int i = blockIdx.x * blockDim.x + threadIdx.x;
    float4 v = ((const float4*)g_y)[i];
    float4 b = ((const float4*)bias)[i & 31];
    float4 o;
    o.x = tanhf(v.x + b.x); o.y = tanhf(v.y + b.y);
    o.z = tanhf(v.z + b.z); o.w = tanhf(v.w + b.w);
    ((float4*)out)[i] = o;
}

// ============================================================
extern "C" void kernel_launch(void* const* d_in, const int* in_sizes, int n_in,
                              void* d_out, int out_size) {
    const float* inputs = (const float*)d_in[0];
    const float* pw     = (const float*)d_in[1];
    const float* kern   = (const float*)d_in[2];
    const float* bias   = (const float*)d_in[3];
    const float* state  = (const float*)d_in[4];
    float* out = (float*)d_out;

    cudaFuncSetAttribute(k_gemm, cudaFuncAttributeMaxDynamicSharedMemorySize, SMEM_TOT);

    k_phase1<<<(PP * NC) / 8 + TT / 64, 256>>>(inputs, pw, kern);
    k_scan<<<32, 256>>>(state);
    k_gemm<<<dim3(148, 2), 256, SMEM_TOT>>>(inputs);
    k_out<<<32, 256>>>(bias, out);
}

// round 10
// speedup vs baseline: 1.2682x; 1.0842x over previous
#include <cuda_runtime.h>
#include <cuda_fp16.h>
#include <math.h>
#include <stdint.h>

#define PP 256
#define TT 65536
#define UU 128
#define TC 128            // GEMM chunk (t)
#define NC 512            // GEMM chunks
#define NCS 1024          // scan chunks (64 t each)

// ---------------- device scratch ----------------
__device__ __align__(16) float g_L[PP*NCS];
__device__ __align__(16) float g_H[PP*NCS];
__device__ __align__(16) float g_sin[PP*NCS];
__device__ __align__(16) float g_y[PP*UU];
__device__ __align__(16) __half g_kh[(size_t)UU*TT];   // [U][T] fp16

// ---------------- helpers ----------------
__device__ __forceinline__ uint32_t smem_u32(const void* p) {
    uint32_t a;
    asm("{ .reg .u64 t; cvta.to.shared.u64 t, %1; cvt.u32.u64 %0, t; }" : "=r"(a) : "l"(p));
    return a;
}
__device__ __forceinline__ void cp16(uint32_t dst, const void* src) {
    asm volatile("cp.async.cg.shared.global [%0], [%1], 16;" :: "r"(dst), "l"(src));
}
#define CP_COMMIT() asm volatile("cp.async.commit_group;" ::: "memory")
#define CP_WAIT1()  asm volatile("cp.async.wait_group 1;" ::: "memory")
#define CP_WAIT0()  asm volatile("cp.async.wait_group 0;" ::: "memory")

#define LDSM_X4(d, addr) \
    asm volatile("ldmatrix.sync.aligned.m8n8.x4.shared.b16 {%0,%1,%2,%3}, [%4];" \
        : "=r"((d)[0]), "=r"((d)[1]), "=r"((d)[2]), "=r"((d)[3]) : "r"(addr))

#define MMA_F16(c, a, b0, b1) \
    asm volatile("mma.sync.aligned.m16n8k16.row.col.f32.f16.f16.f32 " \
        "{%0,%1,%2,%3}, {%4,%5,%6,%7}, {%8,%9}, {%0,%1,%2,%3};" \
        : "+f"((c)[0]), "+f"((c)[1]), "+f"((c)[2]), "+f"((c)[3]) \
        : "r"((a)[0]), "r"((a)[1]), "r"((a)[2]), "r"((a)[3]), "r"(b0), "r"(b1))

__device__ __forceinline__ void combine(float& l, float& h, float l2, float h2) {
    l = fminf(fmaxf(l, l2), h2);
    h = fminf(fmaxf(h, l2), h2);
}

// ============================================================
// Phase 1 (fused): 64-t chunk reductions + kernel transpose (fp16)
// ============================================================
__global__ void k_phase1(const float* __restrict__ x, const float* __restrict__ w,
                         const float* __restrict__ kern) {
    if (blockIdx.x < (PP * NC) / 8) {
        int wid  = (blockIdx.x * blockDim.x + threadIdx.x) >> 5;
        int lane = threadIdx.x & 31;
        int p = wid >> 9;
        int c = wid & (NC - 1);

        float wp = __ldg(&w[p]);
        const float4 xv = *(const float4*)(x + (size_t)p * TT + (size_t)c * TC + lane * 4);
        float x0 = xv.x * wp, x1 = xv.y * wp, x2 = xv.z * wp, x3 = xv.w * wp;

        float l = x0, h = x0 + 1.0f;
        combine(l, h, x1, x1 + 1.0f);
        combine(l, h, x2, x2 + 1.0f);
        combine(l, h, x3, x3 + 1.0f);
        #pragma unroll
        for (int d = 1; d < 16; d <<= 1) {
            float lo = __shfl_down_sync(0xffffffffu, l, d);
            float ho = __shfl_down_sync(0xffffffffu, h, d);
            if ((lane & 15) + d < 16) combine(l, h, lo, ho);
        }
        if ((lane & 15) == 0) {
            int c2 = c * 2 + (lane >> 4);
            g_L[p * NCS + c2] = l;
            g_H[p * NCS + c2] = h;
        }
    } else {
        __shared__ __half sh[128][72];
        int tb = blockIdx.x - (PP * NC) / 8;
        int t0 = tb * 64;
        int u = threadIdx.x & 127, rh = threadIdx.x >> 7;
        #pragma unroll 8
        for (int rr = 0; rr < 64; rr += 2) {
            int t = t0 + rr + rh;
            sh[u][rr + rh] = __float2half_rn(__ldg(&kern[(size_t)t * UU + u]));
        }
        __syncthreads();
        int uu = threadIdx.x >> 1, half_ = threadIdx.x & 1;
        const uint4* srcH = (const uint4*)&sh[uu][half_ * 32];
        uint4* dstH = (uint4*)(g_kh + (size_t)uu * TT + t0 + half_ * 32);
        #pragma unroll
        for (int q = 0; q < 4; q++) dstH[q] = srcH[q];
    }
}

// ============================================================
// Phase 2: per-player scan over 1024 chunk-ops (+ zero g_y)
// ============================================================
__global__ void k_scan(const float* __restrict__ state) {
    int gtid = blockIdx.x * blockDim.x + threadIdx.x;
    ((float4*)g_y)[gtid] = make_float4(0.f, 0.f, 0.f, 0.f);

    int p    = gtid >> 5;
    int lane = gtid & 31;
    const int CPL = NCS / 32;

    float L[CPL], H[CPL];
    int base = p * NCS + lane * CPL;
    #pragma unroll
    for (int i = 0; i < CPL; i++) { L[i] = g_L[base + i]; H[i] = g_H[base + i]; }

    float l = L[0], h = H[0];
    #pragma unroll
    for (int i = 1; i < CPL; i++) combine(l, h, L[i], H[i]);

    #pragma unroll
    for (int d = 1; d < 32; d <<= 1) {
        float lo = __shfl_up_sync(0xffffffffu, l, d);
        float ho = __shfl_up_sync(0xffffffffu, h, d);
        if (lane >= d) {
            float nl = fminf(fmaxf(lo, l), h);
            float nh = fminf(fmaxf(ho, l), h);
            l = nl; h = nh;
        }
    }
    float exl = __shfl_up_sync(0xffffffffu, l, 1);
    float exh = __shfl_up_sync(0xffffffffu, h, 1);

    float s = state[p];
    if (lane > 0) s = fminf(fmaxf(s, exl), exh);
    #pragma unroll
    for (int i = 0; i < CPL; i++) {
        g_sin[base + i] = s;
        s = fminf(fmaxf(s, L[i]), H[i]);
    }
}

// ============================================================
// Phase 3: fp16 HMMA GEMM (1 term) with fused lane-serial replay.
// Grid (148,2) -> 2 blocks/SM. Chunk columns REVERSED for py=1 so
// each SM's two co-resident blocks sum to 7 (not 8) chunk-units.
// ============================================================
#define B_BASE 32768
#define B_SLOT 32768
#define SMEM_TOT (B_BASE + 2 * B_SLOT)   // 96KB

__global__ void __launch_bounds__(256, 2)
k_gemm(const float* __restrict__ x, const float* __restrict__ w) {
    extern __shared__ char smem[];
    const uint32_t sb = smem_u32(smem);
    const int tid  = threadIdx.x;
    const int warp = tid >> 5;
    const int lane = tid & 31;
    // balanced chunk-column: py=1 walks columns in reverse
    const int cx = blockIdx.y ? (147 - (int)blockIdx.x) : (int)blockIdx.x;
    const int p0 = blockIdx.y * 128;
    const int rg = warp >> 1;            // MMA: player group (32)
    const int cg = warp & 1;             // MMA: unit group (64)
    const int sub = warp >> 2;           // scan: t-half (0/1)
    const int pg  = warp & 3;            // scan: player group (32)

    float acc[2][8][4];
    #pragma unroll
    for (int a = 0; a < 2; a++)
        #pragma unroll
        for (int b = 0; b < 8; b++)
            #pragma unroll
            for (int r = 0; r < 4; r++) acc[a][b][r] = 0.f;

    const int nch = (511 - cx) / 148 + 1;

    // scan-side constants
    const int pl = pg * 32 + lane;
    const int p  = p0 + pl;
    const float wp = __ldg(&w[p]);
    const uint32_t aRowS = (uint32_t)pl * 256;
    const uint32_t sxor  = (uint32_t)(pl & 15);

    // MMA-side constants
    const uint32_t aRowM = (uint32_t)(rg * 32 + (lane & 15)) * 256;
    const uint32_t axor  = (uint32_t)(lane & 15);
    const int laneKA = lane >> 4;
    const uint32_t bRow = (uint32_t)(cg * 64 + (lane & 7) + 8 * (lane >> 4)) * 256;
    const uint32_t bxor = (uint32_t)(((lane & 7) + 8 * (lane >> 4)) & 15);
    const int laneKB = (lane >> 3) & 1;

    // B loader: 128u x 128t fp16 -> slot (2048 x 16B)
    auto loadB = [&](int c, int slot) {
        uint32_t dbase = sb + B_BASE + slot * B_SLOT;
        #pragma unroll
        for (int q = 0; q < 8; q++) {
            int idx = q * 256 + tid;          // 0..2047
            int u = idx >> 4, seg = idx & 15;
            cp16(dbase + u * 256 + (((uint32_t)(seg ^ (u & 15))) << 4),
                 (const char*)(g_kh + (size_t)u * TT + (size_t)c * TC + seg * 8));
        }
    };

    loadB(cx, 0);
    CP_COMMIT();

    for (int i = 0; i < nch; i++) {
        const int c = cx + i * 148;

        __syncthreads();       // previous MMA finished reading A / B slot free

        // ---- lane-serial replay: 64 clamp steps, in order, into A ----
        {
            float s = __ldg(&g_sin[(size_t)p * NCS + c * 2 + sub]);
            const float4* xr = (const float4*)(x + (size_t)p * TT + (size_t)c * TC + sub * 64);
            #pragma unroll
            for (int g = 0; g < 8; g++) {
                float4 v0 = __ldg(xr + 2 * g);
                float4 v1 = __ldg(xr + 2 * g + 1);
                float xs[8] = { v0.x*wp, v0.y*wp, v0.z*wp, v0.w*wp,
                                v1.x*wp, v1.y*wp, v1.z*wp, v1.w*wp };
                float ss[8];
                #pragma unroll
                for (int t2 = 0; t2 < 8; t2++) {
                    s = fminf(fmaxf(s, xs[t2]), xs[t2] + 1.0f);
                    ss[t2] = s;
                }
                uint32_t hw[4];
                #pragma unroll
                for (int j = 0; j < 4; j++) {
                    asm("cvt.rn.f16x2.f32 %0, %1, %2;"
                        : "=r"(hw[j]) : "f"(ss[2*j+1]), "f"(ss[2*j]));
                }
                uint32_t seg = (uint32_t)(sub * 8 + g);
                uint32_t ad = sb + aRowS + ((seg ^ sxor) << 4);
                asm volatile("st.shared.v4.b32 [%0], {%1,%2,%3,%4};"
                    :: "r"(ad), "r"(hw[0]), "r"(hw[1]), "r"(hw[2]), "r"(hw[3]) : "memory");
            }
        }

        if (i + 1 < nch) { loadB(c + 148, (i + 1) & 1); CP_COMMIT(); CP_WAIT1(); }
        else            { CP_WAIT0(); }

        __syncthreads();       // A stores + B(i) visible

        // ---- MMA: 8 k-steps of 16 ----
        const uint32_t BS = sb + B_BASE + (uint32_t)(i & 1) * B_SLOT;
        #pragma unroll
        for (int ks = 0; ks < 8; ks++) {
            uint32_t ao = (((uint32_t)(ks * 2 + laneKA)) ^ axor) << 4;
            uint32_t a0[4], a1[4];
            LDSM_X4(a0, sb + aRowM + ao);
            LDSM_X4(a1, sb + aRowM + 4096 + ao);

            uint32_t bo = (((uint32_t)(ks * 2 + laneKB)) ^ bxor) << 4;
            #pragma unroll
            for (int q = 0; q < 4; q++) {
                uint32_t bh[4];
                LDSM_X4(bh, BS + bRow + q * 4096 + bo);
                #pragma unroll
                for (int t2 = 0; t2 < 2; t2++) {
                    int nt = 2 * q + t2;
                    MMA_F16(acc[0][nt], a0, bh[2*t2], bh[2*t2+1]);
                    MMA_F16(acc[1][nt], a1, bh[2*t2], bh[2*t2+1]);
                }
            }
        }
    }

    // ---- single atomic pass ----
    #pragma unroll
    for (int mt = 0; mt < 2; mt++) {
        #pragma unroll
        for (int nt = 0; nt < 8; nt++) {
            #pragma unroll
            for (int r = 0; r < 4; r++) {
                int row = p0 + rg * 32 + mt * 16 + (lane >> 2) + ((r >> 1) ? 8 : 0);
                int col = cg * 64 + nt * 8 + (lane & 3) * 2 + (r & 1);
                atomicAdd(&g_y[row * UU + col], acc[mt][nt][r]);
            }
        }
    }
}

// ============================================================
// Phase 4: epilogue  out = tanh(y + bias)
// ============================================================
__global__ void k_out(const float* __restrict__ bias, float* __restrict__ out) {
    int i = blockIdx.x * blockDim.x + threadIdx.x;
    float4 v = ((const float4*)g_y)[i];
    float4 b = ((const float4*)bias)[i & 31];
    float4 o;
    o.x = tanhf(v.x + b.x); o.y = tanhf(v.y + b.y);
    o.z = tanhf(v.z + b.z); o.w = tanhf(v.w + b.w);
    ((float4*)out)[i] = o;
}

// ============================================================
extern "C" void kernel_launch(void* const* d_in, const int* in_sizes, int n_in,
                              void* d_out, int out_size) {
    const float* inputs = (const float*)d_in[0];
    const float* pw     = (const float*)d_in[1];
    const float* kern   = (const float*)d_in[2];
    const float* bias   = (const float*)d_in[3];
    const float* state  = (const float*)d_in[4];
    float* out = (float*)d_out;

    cudaFuncSetAttribute(k_gemm, cudaFuncAttributeMaxDynamicSharedMemorySize, SMEM_TOT);

    k_phase1<<<(PP * NC) / 8 + TT / 64, 256>>>(inputs, pw, kern);
    k_scan<<<32, 256>>>(state);
    k_gemm<<<dim3(148, 2), 256, SMEM_TOT>>>(inputs, pw);
    k_out<<<32, 256>>>(bias, out);
}